// round 1
// baseline (speedup 1.0000x reference)
#include <cuda_runtime.h>

#define BB 8
#define NN 1024
#define DD 64
#define HH 32

// Scratch for projected activations (allocation-free rule -> device globals).
__device__ float g_ca[BB * NN * HH];  // cell @ w_k
__device__ float g_dv[BB * NN * HH];  // drug @ w_q + bias

// ---------------------------------------------------------------------------
// Projection kernel: one warp per row, lane = h. Row data exchanged via shfl.
// rows [0, B*N)      -> cell @ w_k          -> g_ca
// rows [B*N, 2*B*N)  -> drug @ w_q + bias   -> g_dv
// ---------------------------------------------------------------------------
__global__ __launch_bounds__(128) void proj_kernel(
    const float* __restrict__ cell, const float* __restrict__ drug,
    const float* __restrict__ w_q, const float* __restrict__ w_k,
    const float* __restrict__ bias)
{
    int warp = threadIdx.x >> 5;
    int lane = threadIdx.x & 31;
    int row  = blockIdx.x * 4 + warp;          // 0 .. 2*B*N-1
    bool is_drug = row >= BB * NN;
    int r = is_drug ? row - BB * NN : row;
    const float* src = (is_drug ? drug : cell) + r * DD;
    const float* W   = is_drug ? w_q : w_k;    // [D][H] row-major

    float x0 = src[lane];
    float x1 = src[lane + 32];

    float acc = is_drug ? bias[lane] : 0.0f;
#pragma unroll
    for (int d = 0; d < 32; d++) {
        float rd = __shfl_sync(0xFFFFFFFFu, x0, d);
        acc = fmaf(rd, W[d * HH + lane], acc);
    }
#pragma unroll
    for (int d = 0; d < 32; d++) {
        float rd = __shfl_sync(0xFFFFFFFFu, x1, d);
        acc = fmaf(rd, W[(d + 32) * HH + lane], acc);
    }
    (is_drug ? g_dv : g_ca)[r * HH + lane] = acc;
}

// ---------------------------------------------------------------------------
// Main co-attention kernel: 64x64 output tile per CTA, 4x4 per thread.
// out[b][i][j] = sum_h a[h] * tanh(ca[b][i][h] + dv[b][j][h])
// ---------------------------------------------------------------------------
__global__ __launch_bounds__(256) void coattn_kernel(
    const float* __restrict__ a_vec, float* __restrict__ out)
{
    __shared__ float s_ca[64][HH + 1];
    __shared__ float s_dv[64][HH + 1];
    __shared__ float s_a[HH];

    int b  = blockIdx.z;
    int i0 = blockIdx.y * 64;
    int j0 = blockIdx.x * 64;
    int tid = threadIdx.x;

    const float* ca = g_ca + (b * NN + i0) * HH;
    const float* dv = g_dv + (b * NN + j0) * HH;

    // Stage 64x32 tiles (2048 floats each), 8 elems per thread.
#pragma unroll
    for (int k = 0; k < 8; k++) {
        int idx = tid + k * 256;
        int r = idx >> 5, h = idx & 31;
        s_ca[r][h] = ca[idx];
        s_dv[r][h] = dv[idx];
    }
    if (tid < HH) s_a[tid] = a_vec[tid];
    __syncthreads();

    int tx = tid & 15;        // j-dimension (4 consecutive cols -> float4 store)
    int ty = tid >> 4;        // i-dimension

    float acc[4][4];
#pragma unroll
    for (int r = 0; r < 4; r++)
#pragma unroll
        for (int c = 0; c < 4; c++) acc[r][c] = 0.0f;

#pragma unroll 4
    for (int h = 0; h < HH; h++) {
        float ah = s_a[h];
        float u[4], v[4];
#pragma unroll
        for (int r = 0; r < 4; r++) u[r] = s_ca[ty * 4 + r][h];
#pragma unroll
        for (int c = 0; c < 4; c++) v[c] = s_dv[tx * 4 + c][h];
#pragma unroll
        for (int r = 0; r < 4; r++)
#pragma unroll
            for (int c = 0; c < 4; c++) {
                float t;
                asm("tanh.approx.f32 %0, %1;" : "=f"(t) : "f"(u[r] + v[c]));
                acc[r][c] = fmaf(ah, t, acc[r][c]);
            }
    }

    // Coalesced float4 stores: j = j0 + tx*4 + c
#pragma unroll
    for (int r = 0; r < 4; r++) {
        int i = i0 + ty * 4 + r;
        float4 val = make_float4(acc[r][0], acc[r][1], acc[r][2], acc[r][3]);
        *reinterpret_cast<float4*>(out + ((size_t)b * NN + i) * NN + j0 + tx * 4) = val;
    }
}

extern "C" void kernel_launch(void* const* d_in, const int* in_sizes, int n_in,
                              void* d_out, int out_size)
{
    const float* cell = (const float*)d_in[0];
    const float* drug = (const float*)d_in[1];
    const float* w_q  = (const float*)d_in[2];
    const float* w_k  = (const float*)d_in[3];
    const float* bias = (const float*)d_in[4];
    const float* a    = (const float*)d_in[5];
    float* out = (float*)d_out;

    // 2*B*N rows, 4 rows (warps) per block
    proj_kernel<<<(2 * BB * NN) / 4, 128>>>(cell, drug, w_q, w_k, bias);

    dim3 grid(NN / 64, NN / 64, BB);
    coattn_kernel<<<grid, 256>>>(a, out);
}